// round 6
// baseline (speedup 1.0000x reference)
#include <cuda_runtime.h>
#include <cstdint>

#define N_NODES 2048
#define F_DIM   128
#define UNITS   128
#define FE_DIM  16
#define DEG     64

#define GRID        1024
#define GEMM_BLOCKS 256
#define NPB         8      // gemm nodes per gemm-block
#define NSPAD2      20     // duplicated row: 16 floats used, padded (16B-aligned)

__device__ float g_hr[N_NODES * UNITS];
__device__ float g_al[N_NODES];
__device__ float g_ar[N_NODES];
__device__ unsigned g_bar = 0;   // monotonic grid barrier counter

__device__ __forceinline__ float lrelu(float x) {
    return x > 0.0f ? x : 0.2f * x;
}

// Packed f32x2 (PTX-only; ptxas won't auto-fuse)
__device__ __forceinline__ unsigned long long pack2(float lo, float hi) {
    unsigned long long r;
    asm("mov.b64 %0, {%1, %2};" : "=l"(r) : "f"(lo), "f"(hi));
    return r;
}
__device__ __forceinline__ void unpack2(float& lo, float& hi, unsigned long long v) {
    asm("mov.b64 {%0, %1}, %2;" : "=f"(lo), "=f"(hi) : "l"(v));
}
__device__ __forceinline__ void fma2(unsigned long long& d,
                                     unsigned long long a,
                                     unsigned long long b) {
    asm("fma.rn.f32x2 %0, %1, %2, %3;" : "=l"(d) : "l"(a), "l"(b), "l"(d));
}

__global__ __launch_bounds__(128, 8)
void fused_kernel(const float* __restrict__ ns,
                  const int* __restrict__ edges,
                  const float* __restrict__ ef,
                  const float* __restrict__ Wl,
                  const float* __restrict__ Wr,
                  const float* __restrict__ W_attn,
                  const float* __restrict__ W_edge,
                  float* __restrict__ out) {
    const int b = blockIdx.x;
    const int t = threadIdx.x;
    const int w = t >> 5, lane = t & 31;

    __shared__ float s_ns2[F_DIM][NSPAD2];    // node values duplicated (a,a)
    __shared__ float s_redL[NPB][4];
    __shared__ float s_redR[NPB][4];
    __shared__ float s_wev[FE_DIM];
    __shared__ float s_score[2 * DEG];
    __shared__ int   s_dst[2 * DEG];
    __shared__ float s_acc[4][UNITS];
    __shared__ float s_part[4];
    __shared__ float s_inv[2];
    __shared__ unsigned s_ticket;

    // ======== Phase A (ALL blocks): edge gather + dot (overlaps gemm) ====
    const int n0a = b * 2;                 // this block's two attn nodes
    const int n   = n0a + (t >> 6);        // node of this thread's edge

    s_dst[t] = reinterpret_cast<const int2*>(edges)[n0a * DEG + t].y;

    if (t < FE_DIM) {
        float s = 0.0f;
        #pragma unroll
        for (int j = 0; j < FE_DIM; j++)
            s += W_edge[t * FE_DIM + j] * W_attn[2 * UNITS + j];
        s_wev[t] = s;
    }
    __syncthreads();

    const int dst = s_dst[t];
    const float4* p = reinterpret_cast<const float4*>(
        ef + ((size_t)n * N_NODES + (size_t)dst) * FE_DIM);
    float dot = 0.0f;
    #pragma unroll
    for (int i = 0; i < 4; i++) {
        const float4 v = p[i];
        dot = fmaf(v.x, s_wev[4 * i + 0], dot);
        dot = fmaf(v.y, s_wev[4 * i + 1], dot);
        dot = fmaf(v.z, s_wev[4 * i + 2], dot);
        dot = fmaf(v.w, s_wev[4 * i + 3], dot);
    }

    // ======== Phase B: GEMM (blocks 0..255) ====
    if (b < GEMM_BLOCKS) {
        const int n0 = b * NPB;
        #pragma unroll
        for (int j = 0; j < NPB; j++) {
            const float a = ns[(n0 + j) * F_DIM + t];
            *reinterpret_cast<float2*>(&s_ns2[t][2 * j]) = make_float2(a, a);
        }
        __syncthreads();

        unsigned long long acc[NPB];      // acc[j] = (hl_j, hr_j) for col t
        #pragma unroll
        for (int j = 0; j < NPB; j++) acc[j] = 0ull;

        #pragma unroll 4
        for (int k = 0; k < F_DIM; k++) {
            const float wl = Wl[k * UNITS + t];
            const float wr = Wr[k * UNITS + t];
            const unsigned long long wp = pack2(wl, wr);
            const ulonglong2* row = reinterpret_cast<const ulonglong2*>(&s_ns2[k][0]);
            const ulonglong2 r0 = row[0];
            const ulonglong2 r1 = row[1];
            const ulonglong2 r2 = row[2];
            const ulonglong2 r3 = row[3];
            fma2(acc[0], r0.x, wp);  fma2(acc[1], r0.y, wp);
            fma2(acc[2], r1.x, wp);  fma2(acc[3], r1.y, wp);
            fma2(acc[4], r2.x, wp);  fma2(acc[5], r2.y, wp);
            fma2(acc[6], r3.x, wp);  fma2(acc[7], r3.y, wp);
        }

        float hl[NPB], hr[NPB];
        #pragma unroll
        for (int j = 0; j < NPB; j++) unpack2(hl[j], hr[j], acc[j]);

        #pragma unroll
        for (int j = 0; j < NPB; j++)
            g_hr[(n0 + j) * UNITS + t] = hr[j];

        const float wa_l = W_attn[t];
        const float wa_r = W_attn[UNITS + t];
        #pragma unroll
        for (int j = 0; j < NPB; j++) {
            float pl = lrelu(hl[j]) * wa_l;
            float pr = lrelu(hr[j]) * wa_r;
            #pragma unroll
            for (int o = 16; o > 0; o >>= 1) {
                pl += __shfl_down_sync(0xffffffffu, pl, o);
                pr += __shfl_down_sync(0xffffffffu, pr, o);
            }
            if (lane == 0) { s_redL[j][w] = pl; s_redR[j][w] = pr; }
        }
        __syncthreads();
        if (t < NPB) {
            g_al[n0 + t] = s_redL[t][0] + s_redL[t][1] + s_redL[t][2] + s_redL[t][3];
        } else if (t < 2 * NPB) {
            const int j = t - NPB;
            g_ar[n0 + j] = s_redR[j][0] + s_redR[j][1] + s_redR[j][2] + s_redR[j][3];
        }
        __syncthreads();   // all gemm stores issued before arrive
    }

    // ======== Barrier arrive (release) ====
    if (t == 0) {
        __threadfence();
        s_ticket = atomicAdd(&g_bar, 1u);
    }
    // ======== Barrier wait (acquire) ====
    if (t == 0) {
        const unsigned target = (s_ticket & ~(unsigned)(GRID - 1)) + GRID;
        while ((int)(*(volatile unsigned*)&g_bar - target) < 0)
            __nanosleep(64);
        __threadfence();
    }
    __syncthreads();

    // ======== Phase C: scores + softmax ====
    float s = g_al[n] + g_ar[dst] + dot;
    s = fminf(2.0f, fmaxf(-2.0f, s));
    const float sc = __expf(s);
    s_score[t] = sc;

    float v = sc;
    #pragma unroll
    for (int o = 16; o > 0; o >>= 1)
        v += __shfl_down_sync(0xffffffffu, v, o);
    if (lane == 0) s_part[w] = v;
    __syncthreads();
    if (t < 2) s_inv[t] = 1.0f / (s_part[2 * t] + s_part[2 * t + 1]);

    // ======== Phase D: weighted aggregation ====
    // warp w -> node (w>>1), edges [(w&1)*32, +32); two independent chains.
    const int ebase = (w >> 1) * DEG + (w & 1) * 32;
    float4 a0 = make_float4(0.f, 0.f, 0.f, 0.f);
    float4 a1 = make_float4(0.f, 0.f, 0.f, 0.f);
    #pragma unroll
    for (int i = 0; i < 16; i++) {
        const int e0 = ebase + i;
        const int e1 = ebase + 16 + i;
        const float sc0 = s_score[e0];
        const float sc1 = s_score[e1];
        const float4 h0 = *reinterpret_cast<const float4*>(
            g_hr + s_dst[e0] * UNITS + lane * 4);
        const float4 h1 = *reinterpret_cast<const float4*>(
            g_hr + s_dst[e1] * UNITS + lane * 4);
        a0.x = fmaf(sc0, h0.x, a0.x);  a1.x = fmaf(sc1, h1.x, a1.x);
        a0.y = fmaf(sc0, h0.y, a0.y);  a1.y = fmaf(sc1, h1.y, a1.y);
        a0.z = fmaf(sc0, h0.z, a0.z);  a1.z = fmaf(sc1, h1.z, a1.z);
        a0.w = fmaf(sc0, h0.w, a0.w);  a1.w = fmaf(sc1, h1.w, a1.w);
    }
    a0.x += a1.x; a0.y += a1.y; a0.z += a1.z; a0.w += a1.w;
    *reinterpret_cast<float4*>(&s_acc[w][lane * 4]) = a0;
    __syncthreads();

    out[n0a * UNITS + t]       = (s_acc[0][t] + s_acc[1][t]) * s_inv[0];
    out[(n0a + 1) * UNITS + t] = (s_acc[2][t] + s_acc[3][t]) * s_inv[1];
}

extern "C" void kernel_launch(void* const* d_in, const int* in_sizes, int n_in,
                              void* d_out, int out_size) {
    const float* ns      = (const float*)d_in[0];
    const int*   edges   = (const int*)d_in[1];
    const float* ef      = (const float*)d_in[2];
    const float* W_left  = (const float*)d_in[3];
    const float* W_right = (const float*)d_in[4];
    const float* W_attn  = (const float*)d_in[5];
    const float* W_edge  = (const float*)d_in[6];
    float* out = (float*)d_out;

    fused_kernel<<<GRID, 128>>>(ns, edges, ef, W_left, W_right,
                                W_attn, W_edge, out);
}

// round 7
// speedup vs baseline: 1.1034x; 1.1034x over previous
#include <cuda_runtime.h>
#include <cstdint>

#define N_NODES 2048
#define F_DIM   128
#define UNITS   128
#define FE_DIM  16
#define DEG     64

__device__ float g_hr[N_NODES * UNITS];
__device__ float g_al[N_NODES];
__device__ float g_ar[N_NODES];

__device__ __forceinline__ float lrelu(float x) {
    return x > 0.0f ? x : 0.2f * x;
}

// Kernel 1: side-split GEMM. 512 blocks x 128 threads.
//   blocks [0,256):   hl = ns @ Wl  -> al   (hl discarded)
//   blocks [256,512): hr = ns @ Wr  -> g_hr, ar
// Each block: 8 nodes, one output column per thread, node tile transposed
// in smem so broadcasts are 2x LDS.128. W traffic unchanged (64KB/block).
#define NPB   8
#define NSPAD 12   // float4-aligned row pad
__global__ __launch_bounds__(128)
void gemm_kernel(const float* __restrict__ ns,
                 const float* __restrict__ Wl,
                 const float* __restrict__ Wr,
                 const float* __restrict__ W_attn) {
    const int b    = blockIdx.x;
    const int side = b >> 8;               // 0 = L, 1 = R
    const int t    = threadIdx.x;          // output column
    const int n0   = (b & 255) * NPB;

    __shared__ float s_ns[F_DIM][NSPAD];   // [k][node]
    #pragma unroll
    for (int j = 0; j < NPB; j++)
        s_ns[t][j] = ns[(n0 + j) * F_DIM + t];
    __syncthreads();

    const float* __restrict__ W = side ? Wr : Wl;

    float acc[NPB];
    #pragma unroll
    for (int j = 0; j < NPB; j++) acc[j] = 0.0f;

    #pragma unroll 8
    for (int k = 0; k < F_DIM; k++) {
        const float wv = W[k * UNITS + t];   // coalesced 128B/warp
        const float4 a0 = *reinterpret_cast<const float4*>(&s_ns[k][0]);
        const float4 a1 = *reinterpret_cast<const float4*>(&s_ns[k][4]);
        acc[0] = fmaf(a0.x, wv, acc[0]);
        acc[1] = fmaf(a0.y, wv, acc[1]);
        acc[2] = fmaf(a0.z, wv, acc[2]);
        acc[3] = fmaf(a0.w, wv, acc[3]);
        acc[4] = fmaf(a1.x, wv, acc[4]);
        acc[5] = fmaf(a1.y, wv, acc[5]);
        acc[6] = fmaf(a1.z, wv, acc[6]);
        acc[7] = fmaf(a1.w, wv, acc[7]);
    }

    if (side) {
        #pragma unroll
        for (int j = 0; j < NPB; j++)
            g_hr[(n0 + j) * UNITS + t] = acc[j];
    }

    // per-node scalar: sum_t lrelu(acc)*wa
    const float wa = W_attn[side * UNITS + t];
    __shared__ float s_red[NPB][4];
    const int w = t >> 5, lane = t & 31;

    #pragma unroll
    for (int j = 0; j < NPB; j++) {
        float p = lrelu(acc[j]) * wa;
        #pragma unroll
        for (int o = 16; o > 0; o >>= 1)
            p += __shfl_down_sync(0xffffffffu, p, o);
        if (lane == 0) s_red[j][w] = p;
    }
    __syncthreads();
    if (t < NPB) {
        float* dstv = side ? g_ar : g_al;
        dstv[n0 + t] = s_red[t][0] + s_red[t][1] + s_red[t][2] + s_red[t][3];
    }
}

// Kernel 2: R2 shape (grid 2048, 1 node/block, 128 threads, occ ~85%),
// with two independent 8-deep float4 chains per warp in the aggregation.
__global__ __launch_bounds__(128)
void attn_kernel(const int* __restrict__ edges,
                 const float* __restrict__ ef,
                 const float* __restrict__ W_edge,
                 const float* __restrict__ W_attn,
                 float* __restrict__ out) {
    const int n = blockIdx.x;
    const int t = threadIdx.x;
    const int w = t >> 5, lane = t & 31;

    __shared__ float s_wev[FE_DIM];
    __shared__ float s_score[DEG];
    __shared__ int   s_dst[DEG];
    __shared__ float s_acc[4][UNITS];
    __shared__ float s_part[2];
    __shared__ float s_inv;

    // wev = W_edge @ wa_e (256 FLOPs, L2-resident)
    if (t < FE_DIM) {
        float s = 0.0f;
        #pragma unroll
        for (int j = 0; j < FE_DIM; j++)
            s += W_edge[t * FE_DIM + j] * W_attn[2 * UNITS + j];
        s_wev[t] = s;
    }
    if (t < DEG)
        s_dst[t] = reinterpret_cast<const int2*>(edges)[n * DEG + t].y;
    __syncthreads();

    // edge scores: src == n always
    if (t < DEG) {
        const int dst = s_dst[t];
        const float4* p = reinterpret_cast<const float4*>(
            ef + ((size_t)n * N_NODES + (size_t)dst) * FE_DIM);
        float dot = 0.0f;
        #pragma unroll
        for (int i = 0; i < 4; i++) {
            const float4 v = p[i];
            dot = fmaf(v.x, s_wev[4 * i + 0], dot);
            dot = fmaf(v.y, s_wev[4 * i + 1], dot);
            dot = fmaf(v.z, s_wev[4 * i + 2], dot);
            dot = fmaf(v.w, s_wev[4 * i + 3], dot);
        }
        float s = g_al[n] + g_ar[dst] + dot;
        s = fminf(2.0f, fmaxf(-2.0f, s));
        const float sc = __expf(s);
        s_score[t] = sc;

        float v = sc;
        #pragma unroll
        for (int o = 16; o > 0; o >>= 1)
            v += __shfl_down_sync(0xffffffffu, v, o);
        if (lane == 0) s_part[t >> 5] = v;
    }
    __syncthreads();
    if (t == 0) s_inv = 1.0f / (s_part[0] + s_part[1]);

    // aggregation: warp w -> edges [w*16, +16) as two independent chains
    const int ebase = w * 16;
    float4 a0 = make_float4(0.f, 0.f, 0.f, 0.f);
    float4 a1 = make_float4(0.f, 0.f, 0.f, 0.f);
    #pragma unroll
    for (int i = 0; i < 8; i++) {
        const int e0 = ebase + i;
        const int e1 = ebase + 8 + i;
        const float sc0 = s_score[e0];
        const float sc1 = s_score[e1];
        const float4 h0 = *reinterpret_cast<const float4*>(
            g_hr + s_dst[e0] * UNITS + lane * 4);
        const float4 h1 = *reinterpret_cast<const float4*>(
            g_hr + s_dst[e1] * UNITS + lane * 4);
        a0.x = fmaf(sc0, h0.x, a0.x);  a1.x = fmaf(sc1, h1.x, a1.x);
        a0.y = fmaf(sc0, h0.y, a0.y);  a1.y = fmaf(sc1, h1.y, a1.y);
        a0.z = fmaf(sc0, h0.z, a0.z);  a1.z = fmaf(sc1, h1.z, a1.z);
        a0.w = fmaf(sc0, h0.w, a0.w);  a1.w = fmaf(sc1, h1.w, a1.w);
    }
    a0.x += a1.x; a0.y += a1.y; a0.z += a1.z; a0.w += a1.w;
    *reinterpret_cast<float4*>(&s_acc[w][lane * 4]) = a0;
    __syncthreads();   // also publishes s_inv

    out[n * UNITS + t] =
        (s_acc[0][t] + s_acc[1][t] + s_acc[2][t] + s_acc[3][t]) * s_inv;
}

extern "C" void kernel_launch(void* const* d_in, const int* in_sizes, int n_in,
                              void* d_out, int out_size) {
    const float* ns      = (const float*)d_in[0];
    const int*   edges   = (const int*)d_in[1];
    const float* ef      = (const float*)d_in[2];
    const float* W_left  = (const float*)d_in[3];
    const float* W_right = (const float*)d_in[4];
    const float* W_attn  = (const float*)d_in[5];
    const float* W_edge  = (const float*)d_in[6];
    float* out = (float*)d_out;

    gemm_kernel<<<512, 128>>>(ns, W_left, W_right, W_attn);
    attn_kernel<<<N_NODES, 128>>>(edges, ef, W_edge, W_attn, out);
}

// round 8
// speedup vs baseline: 1.2843x; 1.1639x over previous
#include <cuda_runtime.h>
#include <cstdint>

#define N_NODES 2048
#define F_DIM   128
#define UNITS   128
#define FE_DIM  16
#define DEG     64

__device__ float g_hr[N_NODES * UNITS];
__device__ float g_al[N_NODES];
__device__ float g_ar[N_NODES];

__device__ __forceinline__ float lrelu(float x) {
    return x > 0.0f ? x : 0.2f * x;
}

// Packed f32x2 (PTX-only; numerics = two IEEE fma.rn)
__device__ __forceinline__ unsigned long long pack2(float lo, float hi) {
    unsigned long long r;
    asm("mov.b64 %0, {%1, %2};" : "=l"(r) : "f"(lo), "f"(hi));
    return r;
}
__device__ __forceinline__ void unpack2(float& lo, float& hi, unsigned long long v) {
    asm("mov.b64 {%0, %1}, %2;" : "=f"(lo), "=f"(hi) : "l"(v));
}
__device__ __forceinline__ void fma2(unsigned long long& d,
                                     unsigned long long a,
                                     unsigned long long b) {
    asm("fma.rn.f32x2 %0, %1, %2, %3;" : "=l"(d) : "l"(a), "l"(b), "l"(d));
}

// Kernel 1: side-split GEMM, 512 blocks x 128 threads.
//   blocks [0,256):   hl = ns @ Wl -> al    blocks [256,512): hr -> g_hr, ar
// 8 nodes/block; node tile transposed in smem; accumulators packed f32x2
// over node pairs: inner loop = 1 LDG + 1 pack + 2 LDS.128 + 4 FFMA2 per k.
// Plain (L1-cached) W loads: blocks on the same SM share the 64KB W in L1.
#define NPB   8
#define NSPAD 12   // 48B rows: 16B-aligned for ulonglong2 reads
__global__ __launch_bounds__(128)
void gemm_kernel(const float* __restrict__ ns,
                 const float* __restrict__ Wl,
                 const float* __restrict__ Wr,
                 const float* __restrict__ W_attn) {
    const int b    = blockIdx.x;
    const int side = b >> 8;               // 0 = L, 1 = R
    const int t    = threadIdx.x;          // output column
    const int n0   = (b & 255) * NPB;

    __shared__ float s_ns[F_DIM][NSPAD];   // [k][node]
    #pragma unroll
    for (int j = 0; j < NPB; j++)
        s_ns[t][j] = ns[(n0 + j) * F_DIM + t];
    __syncthreads();

    const float* __restrict__ W = side ? Wr : Wl;

    unsigned long long acc[4];             // acc[j] = (h_{2j}, h_{2j+1})
    #pragma unroll
    for (int j = 0; j < 4; j++) acc[j] = 0ull;

    #pragma unroll 8
    for (int k = 0; k < F_DIM; k++) {
        const float wv = W[k * UNITS + t];           // coalesced, L1-cached
        const unsigned long long wp = pack2(wv, wv);
        const ulonglong2* row = reinterpret_cast<const ulonglong2*>(&s_ns[k][0]);
        const ulonglong2 r0 = row[0];   // nodes (0,1),(2,3)
        const ulonglong2 r1 = row[1];   // nodes (4,5),(6,7)
        fma2(acc[0], r0.x, wp);
        fma2(acc[1], r0.y, wp);
        fma2(acc[2], r1.x, wp);
        fma2(acc[3], r1.y, wp);
    }

    float h[NPB];
    #pragma unroll
    for (int j = 0; j < 4; j++) unpack2(h[2 * j], h[2 * j + 1], acc[j]);

    if (side) {
        #pragma unroll
        for (int j = 0; j < NPB; j++)
            g_hr[(n0 + j) * UNITS + t] = h[j];
    }

    // per-node scalar: sum_t lrelu(h)*wa
    const float wa = W_attn[side * UNITS + t];
    __shared__ float s_red[NPB][4];
    const int w = t >> 5, lane = t & 31;

    #pragma unroll
    for (int j = 0; j < NPB; j++) {
        float p = lrelu(h[j]) * wa;
        #pragma unroll
        for (int o = 16; o > 0; o >>= 1)
            p += __shfl_down_sync(0xffffffffu, p, o);
        if (lane == 0) s_red[j][w] = p;
    }
    __syncthreads();
    if (t < NPB) {
        float* dstv = side ? g_ar : g_al;
        dstv[n0 + t] = s_red[t][0] + s_red[t][1] + s_red[t][2] + s_red[t][3];
    }
}

// Kernel 2: exact R2 attn (grid 2048, 1 node/block, 128 threads, 32 regs).
__global__ __launch_bounds__(128)
void attn_kernel(const int* __restrict__ edges,
                 const float* __restrict__ ef,
                 const float* __restrict__ W_edge,
                 const float* __restrict__ W_attn,
                 float* __restrict__ out) {
    const int n = blockIdx.x;
    const int t = threadIdx.x;
    const int w = t >> 5, lane = t & 31;

    __shared__ float s_wev[FE_DIM];
    __shared__ float s_score[DEG];
    __shared__ int   s_dst[DEG];
    __shared__ float s_acc[4][UNITS];
    __shared__ float s_part[2];
    __shared__ float s_inv;

    // fold wev = W_edge @ wa_e into every block (256 FLOPs, L2-resident)
    if (t < FE_DIM) {
        float s = 0.0f;
        #pragma unroll
        for (int j = 0; j < FE_DIM; j++)
            s += W_edge[t * FE_DIM + j] * W_attn[2 * UNITS + j];
        s_wev[t] = s;
    }
    __syncthreads();

    // edge scores: src == n always
    if (t < DEG) {
        const int e   = n * DEG + t;
        const int dst = edges[2 * e + 1];
        const float4* p = reinterpret_cast<const float4*>(
            ef + ((size_t)n * N_NODES + (size_t)dst) * FE_DIM);
        float dot = 0.0f;
        #pragma unroll
        for (int i = 0; i < 4; i++) {
            const float4 v = p[i];
            dot = fmaf(v.x, s_wev[4 * i + 0], dot);
            dot = fmaf(v.y, s_wev[4 * i + 1], dot);
            dot = fmaf(v.z, s_wev[4 * i + 2], dot);
            dot = fmaf(v.w, s_wev[4 * i + 3], dot);
        }
        float s = g_al[n] + g_ar[dst] + dot;
        s = fminf(2.0f, fmaxf(-2.0f, s));
        const float sc = __expf(s);
        s_score[t] = sc;
        s_dst[t]   = dst;

        // partial sums (2 warps active)
        float v = sc;
        #pragma unroll
        for (int o = 16; o > 0; o >>= 1)
            v += __shfl_down_sync(0xffffffffu, v, o);
        if (lane == 0) s_part[t >> 5] = v;
    }
    __syncthreads();
    if (t == 0) s_inv = 1.0f / (s_part[0] + s_part[1]);

    // weighted aggregation: warp w handles edges [w*16, w*16+16),
    // lane loads a float4 -> full 128-col row per warp iteration.
    float4 acc = make_float4(0.0f, 0.0f, 0.0f, 0.0f);
    #pragma unroll
    for (int i = 0; i < DEG / 4; i++) {
        const int e = w * (DEG / 4) + i;
        const float sc = s_score[e];
        const float4 h = *reinterpret_cast<const float4*>(
            g_hr + s_dst[e] * UNITS + lane * 4);
        acc.x = fmaf(sc, h.x, acc.x);
        acc.y = fmaf(sc, h.y, acc.y);
        acc.z = fmaf(sc, h.z, acc.z);
        acc.w = fmaf(sc, h.w, acc.w);
    }
    *reinterpret_cast<float4*>(&s_acc[w][lane * 4]) = acc;
    __syncthreads();   // also publishes s_inv

    const float val = s_acc[0][t] + s_acc[1][t] + s_acc[2][t] + s_acc[3][t];
    out[n * UNITS + t] = val * s_inv;
}

extern "C" void kernel_launch(void* const* d_in, const int* in_sizes, int n_in,
                              void* d_out, int out_size) {
    const float* ns      = (const float*)d_in[0];
    const int*   edges   = (const int*)d_in[1];
    const float* ef      = (const float*)d_in[2];
    const float* W_left  = (const float*)d_in[3];
    const float* W_right = (const float*)d_in[4];
    const float* W_attn  = (const float*)d_in[5];
    const float* W_edge  = (const float*)d_in[6];
    float* out = (float*)d_out;

    gemm_kernel<<<512, 128>>>(ns, W_left, W_right, W_attn);
    attn_kernel<<<N_NODES, 128>>>(edges, ef, W_edge, W_attn, out);
}

// round 9
// speedup vs baseline: 1.2995x; 1.0118x over previous
#include <cuda_runtime.h>
#include <cuda_fp16.h>
#include <cstdint>

#define N_NODES 2048
#define F_DIM   128
#define UNITS   128
#define FE_DIM  16
#define DEG     64

__device__ __half g_hr[N_NODES * UNITS];   // fp16: halves aggregation traffic
__device__ float  g_al[N_NODES];
__device__ float  g_ar[N_NODES];

__device__ __forceinline__ float lrelu(float x) {
    return x > 0.0f ? x : 0.2f * x;
}

// Packed f32x2 (PTX-only; numerics = two IEEE fma.rn)
__device__ __forceinline__ unsigned long long pack2(float lo, float hi) {
    unsigned long long r;
    asm("mov.b64 %0, {%1, %2};" : "=l"(r) : "f"(lo), "f"(hi));
    return r;
}
__device__ __forceinline__ void unpack2(float& lo, float& hi, unsigned long long v) {
    asm("mov.b64 {%0, %1}, %2;" : "=f"(lo), "=f"(hi) : "l"(v));
}
__device__ __forceinline__ void fma2(unsigned long long& d,
                                     unsigned long long a,
                                     unsigned long long b) {
    asm("fma.rn.f32x2 %0, %1, %2, %3;" : "=l"(d) : "l"(a), "l"(b), "l"(d));
}

// Kernel 1: side-split GEMM, 512 blocks x 128 threads (unchanged from R8
// except hr is stored as fp16).
#define NPB   8
#define NSPAD 12
__global__ __launch_bounds__(128)
void gemm_kernel(const float* __restrict__ ns,
                 const float* __restrict__ Wl,
                 const float* __restrict__ Wr,
                 const float* __restrict__ W_attn) {
    const int b    = blockIdx.x;
    const int side = b >> 8;               // 0 = L, 1 = R
    const int t    = threadIdx.x;          // output column
    const int n0   = (b & 255) * NPB;

    __shared__ float s_ns[F_DIM][NSPAD];   // [k][node]
    #pragma unroll
    for (int j = 0; j < NPB; j++)
        s_ns[t][j] = ns[(n0 + j) * F_DIM + t];
    __syncthreads();

    const float* __restrict__ W = side ? Wr : Wl;

    unsigned long long acc[4];             // acc[j] = (h_{2j}, h_{2j+1})
    #pragma unroll
    for (int j = 0; j < 4; j++) acc[j] = 0ull;

    #pragma unroll 8
    for (int k = 0; k < F_DIM; k++) {
        const float wv = W[k * UNITS + t];           // coalesced, L1-cached
        const unsigned long long wp = pack2(wv, wv);
        const ulonglong2* row = reinterpret_cast<const ulonglong2*>(&s_ns[k][0]);
        const ulonglong2 r0 = row[0];
        const ulonglong2 r1 = row[1];
        fma2(acc[0], r0.x, wp);
        fma2(acc[1], r0.y, wp);
        fma2(acc[2], r1.x, wp);
        fma2(acc[3], r1.y, wp);
    }

    float h[NPB];
    #pragma unroll
    for (int j = 0; j < 4; j++) unpack2(h[2 * j], h[2 * j + 1], acc[j]);

    if (side) {
        #pragma unroll
        for (int j = 0; j < NPB; j++)
            g_hr[(n0 + j) * UNITS + t] = __float2half_rn(h[j]);
    }

    const float wa = W_attn[side * UNITS + t];
    __shared__ float s_red[NPB][4];
    const int w = t >> 5, lane = t & 31;

    #pragma unroll
    for (int j = 0; j < NPB; j++) {
        float p = lrelu(h[j]) * wa;
        #pragma unroll
        for (int o = 16; o > 0; o >>= 1)
            p += __shfl_down_sync(0xffffffffu, p, o);
        if (lane == 0) s_red[j][w] = p;
    }
    __syncthreads();
    if (t < NPB) {
        float* dstv = side ? g_ar : g_al;
        dstv[n0 + t] = s_red[t][0] + s_red[t][1] + s_red[t][2] + s_red[t][3];
    }
}

// Kernel 2: R2 block shape (grid 2048, 1 node/block, 128 threads);
// aggregation reads fp16 hr: half-warp per edge, 8 halves per lane (LDG.128),
// fp32 accumulators, shfl(16) combine.
__global__ __launch_bounds__(128)
void attn_kernel(const int* __restrict__ edges,
                 const float* __restrict__ ef,
                 const float* __restrict__ W_edge,
                 const float* __restrict__ W_attn,
                 float* __restrict__ out) {
    const int n = blockIdx.x;
    const int t = threadIdx.x;
    const int w = t >> 5, lane = t & 31;

    __shared__ float s_wev[FE_DIM];
    __shared__ float s_score[DEG];
    __shared__ int   s_dst[DEG];
    __shared__ float s_acc[4][UNITS];
    __shared__ float s_part[2];
    __shared__ float s_inv;

    if (t < FE_DIM) {
        float s = 0.0f;
        #pragma unroll
        for (int j = 0; j < FE_DIM; j++)
            s += W_edge[t * FE_DIM + j] * W_attn[2 * UNITS + j];
        s_wev[t] = s;
    }
    __syncthreads();

    // edge scores: src == n always
    if (t < DEG) {
        const int e   = n * DEG + t;
        const int dst = edges[2 * e + 1];
        const float4* p = reinterpret_cast<const float4*>(
            ef + ((size_t)n * N_NODES + (size_t)dst) * FE_DIM);
        float dot = 0.0f;
        #pragma unroll
        for (int i = 0; i < 4; i++) {
            const float4 v = p[i];
            dot = fmaf(v.x, s_wev[4 * i + 0], dot);
            dot = fmaf(v.y, s_wev[4 * i + 1], dot);
            dot = fmaf(v.z, s_wev[4 * i + 2], dot);
            dot = fmaf(v.w, s_wev[4 * i + 3], dot);
        }
        float s = g_al[n] + g_ar[dst] + dot;
        s = fminf(2.0f, fmaxf(-2.0f, s));
        const float sc = __expf(s);
        s_score[t] = sc;
        s_dst[t]   = dst;

        float v = sc;
        #pragma unroll
        for (int o = 16; o > 0; o >>= 1)
            v += __shfl_down_sync(0xffffffffu, v, o);
        if (lane == 0) s_part[t >> 5] = v;
    }
    __syncthreads();
    if (t == 0) s_inv = 1.0f / (s_part[0] + s_part[1]);

    // aggregation: warp w -> edges [w*16, +16). Per iteration, half-warp
    // handles one edge; lane loads 8 halves (16B) of that edge's hr row.
    const int ebase = w * 16;
    const int sub   = lane >> 4;            // 0 or 1: which edge of the pair
    const int c0    = (lane & 15) * 8;      // column start for this lane

    float acc[8];
    #pragma unroll
    for (int k = 0; k < 8; k++) acc[k] = 0.0f;

    #pragma unroll
    for (int i = 0; i < 8; i++) {
        const int e = ebase + 2 * i + sub;
        const float sc = s_score[e];
        const int4 hv = *reinterpret_cast<const int4*>(
            g_hr + s_dst[e] * UNITS + c0);
        const __half2* hp = reinterpret_cast<const __half2*>(&hv);
        #pragma unroll
        for (int k = 0; k < 4; k++) {
            const float2 f = __half22float2(hp[k]);
            acc[2 * k]     = fmaf(sc, f.x, acc[2 * k]);
            acc[2 * k + 1] = fmaf(sc, f.y, acc[2 * k + 1]);
        }
    }
    #pragma unroll
    for (int k = 0; k < 8; k++)
        acc[k] += __shfl_down_sync(0xffffffffu, acc[k], 16);

    if (lane < 16) {
        *reinterpret_cast<float4*>(&s_acc[w][c0]) =
            make_float4(acc[0], acc[1], acc[2], acc[3]);
        *reinterpret_cast<float4*>(&s_acc[w][c0 + 4]) =
            make_float4(acc[4], acc[5], acc[6], acc[7]);
    }
    __syncthreads();   // also publishes s_inv

    out[n * UNITS + t] =
        (s_acc[0][t] + s_acc[1][t] + s_acc[2][t] + s_acc[3][t]) * s_inv;
}

extern "C" void kernel_launch(void* const* d_in, const int* in_sizes, int n_in,
                              void* d_out, int out_size) {
    const float* ns      = (const float*)d_in[0];
    const int*   edges   = (const int*)d_in[1];
    const float* ef      = (const float*)d_in[2];
    const float* W_left  = (const float*)d_in[3];
    const float* W_right = (const float*)d_in[4];
    const float* W_attn  = (const float*)d_in[5];
    const float* W_edge  = (const float*)d_in[6];
    float* out = (float*)d_out;

    gemm_kernel<<<512, 128>>>(ns, W_left, W_right, W_attn);
    attn_kernel<<<N_NODES, 128>>>(edges, ef, W_edge, W_attn, out);
}